// round 6
// baseline (speedup 1.0000x reference)
#include <cuda_runtime.h>
#include <cuda_bf16.h>
#include <cstdint>

#define N_AST   200000
#define N_TEST  10000
#define HD      128
#define NLAYERS 5

// ---------------- scratch (device globals; no allocation allowed) ----------
#define F_HA   0u
#define F_HB   25600000u
#define F_XTA  51200000u
#define F_STB  52480000u
#define F_HTA  53760000u
#define F_HTB  55040000u
#define F_WS   56320000u
#define F_TOT  56401920u
__device__ float g_f[F_TOT];

#define I_OFF_AA 0
#define I_OFF_TA 200001
#define I_OFF_AT 400002
#define I_CUR_AA 410003
#define I_CUR_TA 610003
#define I_CUR_AT 810003
#define I_CSR_AA 820013
#define I_CSR_TA 2820013
#define I_CSR_AT 3320013
#define I_PART   3820013
#define I_POFF   3820781
#define I_TOT    3821552
__device__ int g_i[I_TOT];

static inline int div_up(int a, int b) { return (a + b - 1) / b; }

// epilogue flags (small GEMM)
#define F_ADDIN  1
#define F_BIAS   2
#define F_RELU   4
#define F_ADDRES 8

// ---------------- small utility kernels ------------------------------------
__global__ void k_zero_int(int* __restrict__ p, int n) {
    int i = blockIdx.x * blockDim.x + threadIdx.x;
    if (i < n) p[i] = 0;
}
__global__ void k_hist(const int* __restrict__ dst, int* __restrict__ deg, int E) {
    int e = blockIdx.x * blockDim.x + threadIdx.x;
    if (e < E) atomicAdd(&deg[dst[e]], 1);
}

// ---- parallel exclusive scan: blocksum -> exscan(parts) -> apply ----------
__global__ void k_blocksum(const int* __restrict__ v, int* __restrict__ part, int n) {
    __shared__ int ws[32];
    int t = threadIdx.x;
    int i = blockIdx.x * 1024 + t;
    int x = (i < n) ? v[i] : 0;
    #pragma unroll
    for (int o = 16; o; o >>= 1) x += __shfl_xor_sync(0xffffffffu, x, o);
    if ((t & 31) == 0) ws[t >> 5] = x;
    __syncthreads();
    if (t < 32) {
        int y = ws[t];
        #pragma unroll
        for (int o = 16; o; o >>= 1) y += __shfl_xor_sync(0xffffffffu, y, o);
        if (t == 0) part[blockIdx.x] = y;
    }
}
__global__ void k_exscan(const int* __restrict__ v, int* __restrict__ offs, int n) {
    __shared__ int wsum[32];
    __shared__ int carry;
    int t = threadIdx.x;
    if (t == 0) carry = 0;
    __syncthreads();
    for (int base = 0; base < n; base += 1024) {
        int i = base + t;
        int orig = (i < n) ? v[i] : 0;
        int x = orig;
        #pragma unroll
        for (int o = 1; o < 32; o <<= 1) {
            int y = __shfl_up_sync(0xffffffffu, x, o);
            if ((t & 31) >= o) x += y;
        }
        if ((t & 31) == 31) wsum[t >> 5] = x;
        __syncthreads();
        if (t < 32) {
            int w = wsum[t];
            #pragma unroll
            for (int o = 1; o < 32; o <<= 1) {
                int y = __shfl_up_sync(0xffffffffu, w, o);
                if (t >= o) w += y;
            }
            wsum[t] = w;
        }
        __syncthreads();
        int woff = (t >= 32) ? wsum[(t >> 5) - 1] : 0;
        int incl = x + woff + carry;
        if (i < n) offs[i] = incl - orig;
        __syncthreads();
        if (t == 1023) carry = incl;
        __syncthreads();
    }
    if (t == 0) offs[n] = carry;
}
// writes offs AND cursor (identical values) — saves a copy pass
__global__ void k_scan_apply(const int* __restrict__ v, const int* __restrict__ poffs,
                             int* __restrict__ offs, int* __restrict__ cur, int n) {
    __shared__ int wsum[32];
    int t = threadIdx.x;
    int i = blockIdx.x * 1024 + t;
    int orig = (i < n) ? v[i] : 0;
    int x = orig;
    #pragma unroll
    for (int o = 1; o < 32; o <<= 1) {
        int y = __shfl_up_sync(0xffffffffu, x, o);
        if ((t & 31) >= o) x += y;
    }
    if ((t & 31) == 31) wsum[t >> 5] = x;
    __syncthreads();
    if (t < 32) {
        int w = wsum[t];
        #pragma unroll
        for (int o = 1; o < 32; o <<= 1) {
            int y = __shfl_up_sync(0xffffffffu, w, o);
            if (t >= o) w += y;
        }
        wsum[t] = w;
    }
    __syncthreads();
    int woff = (t >= 32) ? wsum[(t >> 5) - 1] : 0;
    int incl = x + woff + poffs[blockIdx.x];
    if (i < n) {
        int ex = incl - orig;
        offs[i] = ex;
        cur[i] = ex;
    }
    if (i == 0) offs[n] = poffs[gridDim.x];
}

__global__ void k_build(const int* __restrict__ dst, const int* __restrict__ src,
                        int* __restrict__ cursor, int* __restrict__ csr, int E) {
    int e = blockIdx.x * blockDim.x + threadIdx.x;
    if (e < E) {
        int p = atomicAdd(&cursor[dst[e]], 1);
        csr[p] = src[e];
    }
}
__global__ void k_init_test(const float* __restrict__ temb, float* __restrict__ h) {
    int i = blockIdx.x * blockDim.x + threadIdx.x;
    if (i < N_TEST * HD) h[i] = temb[i & 127];
}

// ---- split W_aa (5 layers) into bf16 hi/lo, transposed to (n,k) -----------
__global__ void k_split_w(const float* __restrict__ W,
                          __nv_bfloat16* __restrict__ Wh, __nv_bfloat16* __restrict__ Wl) {
    int i = blockIdx.x * blockDim.x + threadIdx.x;
    if (i >= NLAYERS * 16384) return;
    int l = i >> 14, r = i & 16383;
    int k = r >> 7, n = r & 127;
    float w = W[l * 16384 + k * 128 + n];
    __nv_bfloat16 h = __float2bfloat16_rn(w);
    __nv_bfloat16 lo = __float2bfloat16_rn(w - __bfloat162float(h));
    Wh[l * 16384 + n * 128 + k] = h;
    Wl[l * 16384 + n * 128 + k] = lo;
}

// ---------------- encoder ----------------------------------------------------
__global__ void __launch_bounds__(256) k_encode(
    const int* __restrict__ label, const float* __restrict__ content,
    const float* __restrict__ emb, const float* __restrict__ Wc,
    const float* __restrict__ bc, float* __restrict__ h)
{
    extern __shared__ float sm[];
    float* Ws = sm;
    float* Cs = sm + 16384;
    int t = threadIdx.x;
    const float4* Wc4 = (const float4*)Wc;
    float4* Ws4 = (float4*)Ws;
    #pragma unroll
    for (int i = 0; i < 16; i++) Ws4[t + 256 * i] = Wc4[t + 256 * i];
    int n0 = blockIdx.x * 16;
    const float4* C4 = (const float4*)content + (size_t)n0 * 64;
    float4* Cs4 = (float4*)Cs;
    #pragma unroll
    for (int i = 0; i < 4; i++) Cs4[t + 256 * i] = C4[t + 256 * i];
    __syncthreads();
    int node = t >> 4, c = t & 15;
    const float* crow = &Cs[node * 256];
    float a0 = bc[c], a1 = bc[c + 16], a2 = bc[c + 32], a3 = bc[c + 48];
    #pragma unroll 4
    for (int k = 0; k < 256; k++) {
        float cv = crow[k];
        const float* wr = &Ws[k * 64];
        a0 += cv * wr[c];
        a1 += cv * wr[c + 16];
        a2 += cv * wr[c + 32];
        a3 += cv * wr[c + 48];
    }
    int gn = n0 + node;
    int lab = label[gn];
    float* hr = &h[(size_t)gn * HD];
    const float* er = &emb[(size_t)lab * 64];
    hr[c]      = er[c];
    hr[c + 16] = er[c + 16];
    hr[c + 32] = er[c + 32];
    hr[c + 48] = er[c + 48];
    hr[64 + c]      = a0;
    hr[64 + c + 16] = a1;
    hr[64 + c + 32] = a2;
    hr[64 + c + 48] = a3;
}

// ---------------- fused layer kernel -----------------------------------------
// per 64-row tile of ast nodes:
//   gather-aa mean(ia) -> bf16 hi/lo split -> A smem
//   MMA (3-term bf16 split, fp32 acc) with resident pre-split W
//   gather-ta mean(Xta) -> Mta smem (aliases A region)
//   epilogue: + Mta + bias, relu, (+res), store
#define APAD 136
#define SM_W_OFF 34816     // bytes: max(2*64*136*2, 64*132*4) region for A/Mta
#define SM_LAYER (34816 + 2 * 128 * APAD * 2)

__device__ __forceinline__ void mma16816(float c[4], const uint32_t a[4],
                                         uint32_t b0, uint32_t b1) {
    asm volatile(
        "mma.sync.aligned.m16n8k16.row.col.f32.bf16.bf16.f32 "
        "{%0,%1,%2,%3},{%4,%5,%6,%7},{%8,%9},{%0,%1,%2,%3};"
        : "+f"(c[0]), "+f"(c[1]), "+f"(c[2]), "+f"(c[3])
        : "r"(a[0]), "r"(a[1]), "r"(a[2]), "r"(a[3]), "r"(b0), "r"(b1));
}

__global__ void __launch_bounds__(256) k_layer(
    const float* __restrict__ ia, const float* __restrict__ Xta,
    const __nv_bfloat16* __restrict__ Wh_g, const __nv_bfloat16* __restrict__ Wl_g,
    const int* __restrict__ off_aa, const int* __restrict__ csr_aa,
    const int* __restrict__ off_ta, const int* __restrict__ csr_ta,
    const float* __restrict__ bias, const float* __restrict__ res,
    float* __restrict__ out, int addres)
{
    extern __shared__ __align__(16) char smraw[];
    __nv_bfloat16* Ah = (__nv_bfloat16*)smraw;            // [64][APAD]
    __nv_bfloat16* Al = Ah + 64 * APAD;
    float* MtaS = (float*)smraw;                          // [64][132], aliases Ah/Al
    __nv_bfloat16* Wh = (__nv_bfloat16*)(smraw + SM_W_OFF); // [128][APAD]
    __nv_bfloat16* Wl = Wh + 128 * APAD;

    int t = threadIdx.x;
    int warp = t >> 5, lane = t & 31;
    int m0 = blockIdx.x * 64;

    // ---- load pre-split W (straight uint4 copies) ----
    #pragma unroll
    for (int j = 0; j < 8; j++) {
        int i = t + 256 * j;
        int nrow = i >> 4, kg = i & 15;
        *(uint4*)&Wh[nrow * APAD + kg * 8] = ((const uint4*)Wh_g)[i];
        *(uint4*)&Wl[nrow * APAD + kg * 8] = ((const uint4*)Wl_g)[i];
    }

    // ---- gather aa: mean over in-edges, split, store to A smem ----
    for (int r = warp; r < 64; r += 8) {
        int node = m0 + r;
        int s0 = off_aa[node], s1 = off_aa[node + 1];
        float4 a = make_float4(0.f, 0.f, 0.f, 0.f);
        for (int e0 = s0; e0 < s1; e0 += 32) {
            int idx = (e0 + lane < s1) ? csr_aa[e0 + lane] : 0;
            int m = min(32, s1 - e0);
            for (int j = 0; j < m; j++) {
                int s = __shfl_sync(0xffffffffu, idx, j);
                float4 v = *(const float4*)&ia[(size_t)s * HD + lane * 4];
                a.x += v.x; a.y += v.y; a.z += v.z; a.w += v.w;
            }
        }
        float inv = 1.f / (float)((s1 - s0) > 0 ? (s1 - s0) : 1);
        const float mv[4] = {a.x * inv, a.y * inv, a.z * inv, a.w * inv};
        __nv_bfloat16 hh[4], ll[4];
        #pragma unroll
        for (int u = 0; u < 4; u++) {
            hh[u] = __float2bfloat16_rn(mv[u]);
            ll[u] = __float2bfloat16_rn(mv[u] - __bfloat162float(hh[u]));
        }
        *(uint2*)&Ah[r * APAD + lane * 4] = *(uint2*)hh;
        *(uint2*)&Al[r * APAD + lane * 4] = *(uint2*)ll;
    }
    __syncthreads();

    // ---- MMA: 2 M-warps x 4 N-warps, 3-term split ----
    int wm = warp & 1, wn = warp >> 1;
    int q = lane & 3, rr = lane >> 2;
    float c[2][4][4];
    #pragma unroll
    for (int i = 0; i < 2; i++)
        #pragma unroll
        for (int j = 0; j < 4; j++)
            c[i][j][0] = c[i][j][1] = c[i][j][2] = c[i][j][3] = 0.f;

    #pragma unroll
    for (int term = 0; term < 3; term++) {
        const __nv_bfloat16* Ab = (term == 2) ? Al : Ah;
        const __nv_bfloat16* Bb = (term == 1) ? Wl : Wh;
        #pragma unroll
        for (int ks = 0; ks < 8; ks++) {
            int kb = ks * 16;
            uint32_t a[2][4];
            #pragma unroll
            for (int mt = 0; mt < 2; mt++) {
                const __nv_bfloat16* ap = Ab + (wm * 32 + mt * 16 + rr) * APAD + kb + q * 2;
                a[mt][0] = *(const uint32_t*)(ap);
                a[mt][1] = *(const uint32_t*)(ap + 8 * APAD);
                a[mt][2] = *(const uint32_t*)(ap + 8);
                a[mt][3] = *(const uint32_t*)(ap + 8 * APAD + 8);
            }
            #pragma unroll
            for (int nt = 0; nt < 4; nt++) {
                const __nv_bfloat16* bp = Bb + (wn * 32 + nt * 8 + rr) * APAD + kb + q * 2;
                uint32_t b0 = *(const uint32_t*)bp;
                uint32_t b1 = *(const uint32_t*)(bp + 8);
                mma16816(c[0][nt], a[0], b0, b1);
                mma16816(c[1][nt], a[1], b0, b1);
            }
        }
    }
    __syncthreads();   // A smem dead; reuse as Mta

    // ---- gather ta: mean over ta in-edges of Xta rows -> Mta smem ----
    for (int r = warp; r < 64; r += 8) {
        int node = m0 + r;
        int s0 = off_ta[node], s1 = off_ta[node + 1];
        float4 a = make_float4(0.f, 0.f, 0.f, 0.f);
        for (int e0 = s0; e0 < s1; e0 += 32) {
            int idx = (e0 + lane < s1) ? csr_ta[e0 + lane] : 0;
            int m = min(32, s1 - e0);
            for (int j = 0; j < m; j++) {
                int s = __shfl_sync(0xffffffffu, idx, j);
                float4 v = *(const float4*)&Xta[(size_t)s * HD + lane * 4];
                a.x += v.x; a.y += v.y; a.z += v.z; a.w += v.w;
            }
        }
        float inv = 1.f / (float)((s1 - s0) > 0 ? (s1 - s0) : 1);
        *(float4*)&MtaS[r * 132 + lane * 4] =
            make_float4(a.x * inv, a.y * inv, a.z * inv, a.w * inv);
    }
    __syncthreads();

    // ---- epilogue ----
    #pragma unroll
    for (int mt = 0; mt < 2; mt++) {
        #pragma unroll
        for (int half = 0; half < 2; half++) {
            int rloc = wm * 32 + mt * 16 + half * 8 + rr;
            int row = m0 + rloc;
            #pragma unroll
            for (int nt = 0; nt < 4; nt++) {
                int col = wn * 32 + nt * 8 + q * 2;
                size_t o = (size_t)row * HD + col;
                float2 v = make_float2(c[mt][nt][half * 2], c[mt][nt][half * 2 + 1]);
                float2 mm = *(const float2*)&MtaS[rloc * 132 + col];
                float2 bb = *(const float2*)&bias[col];
                v.x += mm.x + bb.x;
                v.y += mm.y + bb.y;
                v.x = fmaxf(v.x, 0.f);
                v.y = fmaxf(v.y, 0.f);
                if (addres) {
                    float2 rv = *(const float2*)&res[o];
                    v.x += rv.x; v.y += rv.y;
                }
                *(float2*)&out[o] = v;
            }
        }
    }
}

// ---------------- FFMA GEMM with fused epilogue (small M) -------------------
__global__ void __launch_bounds__(256) k_gemm_ep(
    const float* __restrict__ A, const float* __restrict__ W,
    const float* __restrict__ AddIn, const float* __restrict__ bias,
    const float* __restrict__ res, float* __restrict__ out, int M, int flags)
{
    extern __shared__ float sm[];
    float* Ws = sm;            // 128*128
    float* As = sm + 16384;    // 64*132
    int t = threadIdx.x;
    const float4* W4 = (const float4*)W;
    float4* Ws4 = (float4*)Ws;
    #pragma unroll
    for (int i = 0; i < 16; i++) Ws4[t + 256 * i] = W4[t + 256 * i];
    int m0 = blockIdx.x * 64;
    #pragma unroll
    for (int i = 0; i < 8; i++) {
        int idx = t + 256 * i;
        int r = idx >> 5, cc = idx & 31;
        int gr = m0 + r;
        float4 v = (gr < M) ? ((const float4*)A)[(size_t)gr * 32 + cc]
                            : make_float4(0.f, 0.f, 0.f, 0.f);
        *(float4*)&As[r * 132 + cc * 4] = v;
    }
    __syncthreads();
    int c0 = (t & 31) * 4;
    int r0 = (t >> 5) * 8;
    float acc[8][4];
    #pragma unroll
    for (int i = 0; i < 8; i++) { acc[i][0] = acc[i][1] = acc[i][2] = acc[i][3] = 0.f; }
    #pragma unroll 2
    for (int k = 0; k < 128; k++) {
        float4 w = *(const float4*)&Ws[k * 128 + c0];
        #pragma unroll
        for (int i = 0; i < 8; i++) {
            float a = As[(r0 + i) * 132 + k];
            acc[i][0] += a * w.x;
            acc[i][1] += a * w.y;
            acc[i][2] += a * w.z;
            acc[i][3] += a * w.w;
        }
    }
    float4 bb = make_float4(0.f, 0.f, 0.f, 0.f);
    if (flags & F_BIAS) bb = *(const float4*)&bias[c0];
    #pragma unroll
    for (int i = 0; i < 8; i++) {
        int gr = m0 + r0 + i;
        if (gr < M) {
            size_t o = (size_t)gr * HD + c0;
            float4 v = make_float4(acc[i][0] + bb.x, acc[i][1] + bb.y,
                                   acc[i][2] + bb.z, acc[i][3] + bb.w);
            if (flags & F_ADDIN) {
                float4 d = *(const float4*)&AddIn[o];
                v.x += d.x; v.y += d.y; v.z += d.z; v.w += d.w;
            }
            if (flags & F_RELU) {
                v.x = fmaxf(v.x, 0.f); v.y = fmaxf(v.y, 0.f);
                v.z = fmaxf(v.z, 0.f); v.w = fmaxf(v.w, 0.f);
            }
            if (flags & F_ADDRES) {
                float4 rv = *(const float4*)&res[o];
                v.x += rv.x; v.y += rv.y; v.z += rv.z; v.w += rv.w;
            }
            *(float4*)&out[o] = v;
        }
    }
}

// ---------------- mean aggregation (fp32 out; used for St) ------------------
__global__ void k_agg(const float* __restrict__ X,
                      const int* __restrict__ offs, const int* __restrict__ csr,
                      float* __restrict__ out, int n)
{
    int node = (blockIdx.x * blockDim.x + threadIdx.x) >> 5;
    if (node >= n) return;
    int lane = threadIdx.x & 31;
    int s0 = offs[node], s1 = offs[node + 1];
    float4 a = make_float4(0.f, 0.f, 0.f, 0.f);
    for (int e0 = s0; e0 < s1; e0 += 32) {
        int idx = (e0 + lane < s1) ? csr[e0 + lane] : 0;
        int m = min(32, s1 - e0);
        for (int j = 0; j < m; j++) {
            int s = __shfl_sync(0xffffffffu, idx, j);
            float4 v = *(const float4*)&X[(size_t)s * HD + lane * 4];
            a.x += v.x; a.y += v.y; a.z += v.z; a.w += v.w;
        }
    }
    float inv = 1.f / (float)((s1 - s0) > 0 ? (s1 - s0) : 1);
    *(float4*)&out[(size_t)node * HD + lane * 4] =
        make_float4(a.x * inv, a.y * inv, a.z * inv, a.w * inv);
}

// ---------------- decoder ----------------------------------------------------
__global__ void k_decode(const float* __restrict__ h, const float* __restrict__ dW,
                         const float* __restrict__ db, float* __restrict__ logits,
                         float* __restrict__ pred, int write_pred)
{
    int node = (blockIdx.x * blockDim.x + threadIdx.x) >> 5;
    if (node >= N_AST) return;
    int lane = threadIdx.x & 31;
    float4 v = *(const float4*)&h[(size_t)node * HD + lane * 4];
    float l0 = 0.f, l1 = 0.f;
    const float* hv = &v.x;
    #pragma unroll
    for (int j = 0; j < 4; j++) {
        int k = lane * 4 + j;
        float2 w = *(const float2*)&dW[k * 2];
        l0 += hv[j] * w.x;
        l1 += hv[j] * w.y;
    }
    #pragma unroll
    for (int o = 16; o; o >>= 1) {
        l0 += __shfl_xor_sync(0xffffffffu, l0, o);
        l1 += __shfl_xor_sync(0xffffffffu, l1, o);
    }
    if (lane == 0) {
        l0 += db[0];
        l1 += db[1];
        logits[node * 2]     = l0;
        logits[node * 2 + 1] = l1;
        if (write_pred) {
            float m = fmaxf(l0, l1);
            float e0 = expf(l0 - m), e1 = expf(l1 - m);
            float s = e0 + e1;
            pred[node * 2]     = e0 / s;
            pred[node * 2 + 1] = e1 / s;
        }
    }
}

// ---------------- launch ----------------------------------------------------
extern "C" void kernel_launch(void* const* d_in, const int* in_sizes, int n_in,
                              void* d_out, int out_size)
{
    const int*   ast_label   = (const int*)d_in[0];
    const float* ast_content = (const float*)d_in[1];
    const int* src_aa = (const int*)d_in[2];
    const int* dst_aa = (const int*)d_in[3];
    const int* src_at = (const int*)d_in[4];
    const int* dst_at = (const int*)d_in[5];
    const int* src_ta = (const int*)d_in[6];
    const int* dst_ta = (const int*)d_in[7];
    int E_aa = in_sizes[2], E_at = in_sizes[4], E_ta = in_sizes[6];

    int p = 8;
    if (n_in > 8 && in_sizes[8] == 1) p = 9;
    const float* emb    = (const float*)d_in[p + 0];
    const float* Wc     = (const float*)d_in[p + 1];
    const float* bc     = (const float*)d_in[p + 2];
    const float* temb   = (const float*)d_in[p + 3];
    const float* W_aa   = (const float*)d_in[p + 4];
    const float* W_at   = (const float*)d_in[p + 5];
    const float* W_ta   = (const float*)d_in[p + 6];
    const float* b_ast  = (const float*)d_in[p + 7];
    const float* b_test = (const float*)d_in[p + 8];
    const float* dW     = (const float*)d_in[p + 9];
    const float* db     = (const float*)d_in[p + 10];

    float* F = nullptr;
    int*   I = nullptr;
    cudaGetSymbolAddress((void**)&F, g_f);
    cudaGetSymbolAddress((void**)&I, g_i);

    cudaFuncSetAttribute(k_gemm_ep, cudaFuncAttributeMaxDynamicSharedMemorySize, 99328);
    cudaFuncSetAttribute(k_layer,   cudaFuncAttributeMaxDynamicSharedMemorySize, SM_LAYER);
    cudaFuncSetAttribute(k_encode,  cudaFuncAttributeMaxDynamicSharedMemorySize, 81920);

    float* hA  = F + F_HA;   float* hB  = F + F_HB;
    float* Xta = F + F_XTA;  float* St  = F + F_STB;
    float* hTA = F + F_HTA;  float* hTB = F + F_HTB;
    __nv_bfloat16* Whg = (__nv_bfloat16*)(F + F_WS);
    __nv_bfloat16* Wlg = (__nv_bfloat16*)(F + F_WS + 40960u);

    int* off_aa = I + I_OFF_AA; int* off_ta = I + I_OFF_TA; int* off_at = I + I_OFF_AT;
    int* cur_aa = I + I_CUR_AA; int* cur_ta = I + I_CUR_TA; int* cur_at = I + I_CUR_AT;
    int* csr_aa = I + I_CSR_AA; int* csr_ta = I + I_CSR_TA; int* csr_at = I + I_CSR_AT;
    int* part   = I + I_PART;   int* poff   = I + I_POFF;

    int nb_ast  = div_up(N_AST, 1024);
    int nb_test = div_up(N_TEST, 1024);

    // --- CSR build ---
    k_zero_int<<<div_up(N_AST, 256), 256>>>(cur_aa, N_AST);
    k_zero_int<<<div_up(N_AST, 256), 256>>>(cur_ta, N_AST);
    k_zero_int<<<div_up(N_TEST, 256), 256>>>(cur_at, N_TEST);
    k_hist<<<div_up(E_aa, 256), 256>>>(dst_aa, cur_aa, E_aa);
    k_hist<<<div_up(E_ta, 256), 256>>>(dst_ta, cur_ta, E_ta);
    k_hist<<<div_up(E_at, 256), 256>>>(dst_at, cur_at, E_at);
    k_blocksum<<<nb_ast, 1024>>>(cur_aa, part, N_AST);
    k_exscan<<<1, 1024>>>(part, poff, nb_ast);
    k_scan_apply<<<nb_ast, 1024>>>(cur_aa, poff, off_aa, cur_aa, N_AST);
    k_blocksum<<<nb_ast, 1024>>>(cur_ta, part, N_AST);
    k_exscan<<<1, 1024>>>(part, poff, nb_ast);
    k_scan_apply<<<nb_ast, 1024>>>(cur_ta, poff, off_ta, cur_ta, N_AST);
    k_blocksum<<<nb_test, 1024>>>(cur_at, part, N_TEST);
    k_exscan<<<1, 1024>>>(part, poff, nb_test);
    k_scan_apply<<<nb_test, 1024>>>(cur_at, poff, off_at, cur_at, N_TEST);
    k_build<<<div_up(E_aa, 256), 256>>>(dst_aa, src_aa, cur_aa, csr_aa, E_aa);
    k_build<<<div_up(E_ta, 256), 256>>>(dst_ta, src_ta, cur_ta, csr_ta, E_ta);
    k_build<<<div_up(E_at, 256), 256>>>(dst_at, src_at, cur_at, csr_at, E_at);

    // --- weight pre-split + encode ---
    k_split_w<<<div_up(NLAYERS * 16384, 256), 256>>>(W_aa, Whg, Wlg);
    k_encode<<<N_AST / 16, 256, 81920>>>(ast_label, ast_content, emb, Wc, bc, hA);
    k_init_test<<<div_up(N_TEST * HD, 256), 256>>>(temb, hTA);

    // --- 5 GCN layers ---
    const float* ia = hA; const float* it = hTA;
    float* oa = hB; float* ot = hTB;
    for (int l = 0; l < NLAYERS; l++) {
        int add  = (l == 1 || l == 3);
        int last = (l == NLAYERS - 1);
        // test-path aggregation (reads ia before it's replaced)
        if (!last)
            k_agg<<<div_up(N_TEST * 32, 256), 256>>>(ia, off_at, csr_at, St, N_TEST);
        // Xta = h_test @ W_ta
        k_gemm_ep<<<div_up(N_TEST, 64), 256, 99328>>>(it, W_ta + (size_t)l * HD * HD,
            nullptr, nullptr, nullptr, Xta, N_TEST, 0);
        // fused: h_ast' = relu(mean_aa(ia) @ W_aa + mean_ta(Xta) + b_ast) (+ia)
        k_layer<<<N_AST / 64, 256, SM_LAYER>>>(ia, Xta,
            Whg + (size_t)l * 16384, Wlg + (size_t)l * 16384,
            off_aa, csr_aa, off_ta, csr_ta,
            b_ast + l * HD, ia, oa, add);
        // h_test' = relu(St @ W_at + b_test) (+it)
        if (!last)
            k_gemm_ep<<<div_up(N_TEST, 64), 256, 99328>>>(St, W_at + (size_t)l * HD * HD,
                nullptr, b_test + l * HD, it, ot, N_TEST,
                F_BIAS | F_RELU | (add ? F_ADDRES : 0));
        const float* ta = ia; ia = oa; oa = (float*)ta;
        if (!last) { const float* tt = it; it = ot; ot = (float*)tt; }
    }

    // --- decode ---
    float* logits = (float*)d_out;
    int write_pred = (out_size >= 4 * N_AST);
    float* pred = logits + 2 * N_AST;
    k_decode<<<div_up(N_AST * 32, 256), 256>>>(ia, dW, db, logits, pred, write_pred);
}

// round 7
// speedup vs baseline: 1.2579x; 1.2579x over previous
#include <cuda_runtime.h>
#include <cuda_bf16.h>
#include <cstdint>

#define N_AST   200000
#define N_TEST  10000
#define HD      128
#define NLAYERS 5

// ---------------- scratch (device globals; no allocation allowed) ----------
#define F_HA   0u
#define F_HB   25600000u
#define F_SH   51200000u      // Sh bf16 (25.6M bf16 = 12.8M floats)
#define F_SL   64000000u      // Sl bf16
#define F_MTA  76800000u
#define F_XTA  102400000u
#define F_STB  103680000u
#define F_HTA  104960000u
#define F_HTB  106240000u
#define F_WS   107520000u     // Wh/Wl pre-split (5*16384 bf16 each)
#define F_TOT  107601920u
__device__ float g_f[F_TOT];

#define I_OFF_AA 0
#define I_OFF_TA 200001
#define I_OFF_AT 400002
#define I_CUR_AA 410003
#define I_CUR_TA 610003
#define I_CUR_AT 810003
#define I_CSR_AA 820013
#define I_CSR_TA 2820013
#define I_CSR_AT 3320013
#define I_PART   3820013
#define I_POFF   3820781
#define I_TOT    3821552
__device__ int g_i[I_TOT];

static inline int div_up(int a, int b) { return (a + b - 1) / b; }

// epilogue flags (small GEMM)
#define F_ADDIN  1
#define F_BIAS   2
#define F_RELU   4
#define F_ADDRES 8

// ---------------- small utility kernels ------------------------------------
__global__ void k_zero_int(int* __restrict__ p, int n) {
    int i = blockIdx.x * blockDim.x + threadIdx.x;
    if (i < n) p[i] = 0;
}
__global__ void k_hist(const int* __restrict__ dst, int* __restrict__ deg, int E) {
    int e = blockIdx.x * blockDim.x + threadIdx.x;
    if (e < E) atomicAdd(&deg[dst[e]], 1);
}

// ---- parallel exclusive scan: blocksum -> exscan(parts) -> apply ----------
__global__ void k_blocksum(const int* __restrict__ v, int* __restrict__ part, int n) {
    __shared__ int ws[32];
    int t = threadIdx.x;
    int i = blockIdx.x * 1024 + t;
    int x = (i < n) ? v[i] : 0;
    #pragma unroll
    for (int o = 16; o; o >>= 1) x += __shfl_xor_sync(0xffffffffu, x, o);
    if ((t & 31) == 0) ws[t >> 5] = x;
    __syncthreads();
    if (t < 32) {
        int y = ws[t];
        #pragma unroll
        for (int o = 16; o; o >>= 1) y += __shfl_xor_sync(0xffffffffu, y, o);
        if (t == 0) part[blockIdx.x] = y;
    }
}
__global__ void k_exscan(const int* __restrict__ v, int* __restrict__ offs, int n) {
    __shared__ int wsum[32];
    __shared__ int carry;
    int t = threadIdx.x;
    if (t == 0) carry = 0;
    __syncthreads();
    for (int base = 0; base < n; base += 1024) {
        int i = base + t;
        int orig = (i < n) ? v[i] : 0;
        int x = orig;
        #pragma unroll
        for (int o = 1; o < 32; o <<= 1) {
            int y = __shfl_up_sync(0xffffffffu, x, o);
            if ((t & 31) >= o) x += y;
        }
        if ((t & 31) == 31) wsum[t >> 5] = x;
        __syncthreads();
        if (t < 32) {
            int w = wsum[t];
            #pragma unroll
            for (int o = 1; o < 32; o <<= 1) {
                int y = __shfl_up_sync(0xffffffffu, w, o);
                if (t >= o) w += y;
            }
            wsum[t] = w;
        }
        __syncthreads();
        int woff = (t >= 32) ? wsum[(t >> 5) - 1] : 0;
        int incl = x + woff + carry;
        if (i < n) offs[i] = incl - orig;
        __syncthreads();
        if (t == 1023) carry = incl;
        __syncthreads();
    }
    if (t == 0) offs[n] = carry;
}
// writes offs AND cursor (identical values) — saves a copy pass
__global__ void k_scan_apply(const int* __restrict__ v, const int* __restrict__ poffs,
                             int* __restrict__ offs, int* __restrict__ cur, int n) {
    __shared__ int wsum[32];
    int t = threadIdx.x;
    int i = blockIdx.x * 1024 + t;
    int orig = (i < n) ? v[i] : 0;
    int x = orig;
    #pragma unroll
    for (int o = 1; o < 32; o <<= 1) {
        int y = __shfl_up_sync(0xffffffffu, x, o);
        if ((t & 31) >= o) x += y;
    }
    if ((t & 31) == 31) wsum[t >> 5] = x;
    __syncthreads();
    if (t < 32) {
        int w = wsum[t];
        #pragma unroll
        for (int o = 1; o < 32; o <<= 1) {
            int y = __shfl_up_sync(0xffffffffu, w, o);
            if (t >= o) w += y;
        }
        wsum[t] = w;
    }
    __syncthreads();
    int woff = (t >= 32) ? wsum[(t >> 5) - 1] : 0;
    int incl = x + woff + poffs[blockIdx.x];
    if (i < n) {
        int ex = incl - orig;
        offs[i] = ex;
        cur[i] = ex;
    }
    if (i == 0) offs[n] = poffs[gridDim.x];
}

__global__ void k_build(const int* __restrict__ dst, const int* __restrict__ src,
                        int* __restrict__ cursor, int* __restrict__ csr, int E) {
    int e = blockIdx.x * blockDim.x + threadIdx.x;
    if (e < E) {
        int p = atomicAdd(&cursor[dst[e]], 1);
        csr[p] = src[e];
    }
}
__global__ void k_init_test(const float* __restrict__ temb, float* __restrict__ h) {
    int i = blockIdx.x * blockDim.x + threadIdx.x;
    if (i < N_TEST * HD) h[i] = temb[i & 127];
}

// ---- split W_aa (5 layers) into bf16 hi/lo, transposed to (n,k) -----------
__global__ void k_split_w(const float* __restrict__ W,
                          __nv_bfloat16* __restrict__ Wh, __nv_bfloat16* __restrict__ Wl) {
    int i = blockIdx.x * blockDim.x + threadIdx.x;
    if (i >= NLAYERS * 16384) return;
    int l = i >> 14, r = i & 16383;
    int k = r >> 7, n = r & 127;
    float w = W[l * 16384 + k * 128 + n];
    __nv_bfloat16 h = __float2bfloat16_rn(w);
    __nv_bfloat16 lo = __float2bfloat16_rn(w - __bfloat162float(h));
    Wh[l * 16384 + n * 128 + k] = h;
    Wl[l * 16384 + n * 128 + k] = lo;
}

// ---------------- encoder ----------------------------------------------------
__global__ void __launch_bounds__(256) k_encode(
    const int* __restrict__ label, const float* __restrict__ content,
    const float* __restrict__ emb, const float* __restrict__ Wc,
    const float* __restrict__ bc, float* __restrict__ h)
{
    extern __shared__ float sm[];
    float* Ws = sm;
    float* Cs = sm + 16384;
    int t = threadIdx.x;
    const float4* Wc4 = (const float4*)Wc;
    float4* Ws4 = (float4*)Ws;
    #pragma unroll
    for (int i = 0; i < 16; i++) Ws4[t + 256 * i] = Wc4[t + 256 * i];
    int n0 = blockIdx.x * 16;
    const float4* C4 = (const float4*)content + (size_t)n0 * 64;
    float4* Cs4 = (float4*)Cs;
    #pragma unroll
    for (int i = 0; i < 4; i++) Cs4[t + 256 * i] = C4[t + 256 * i];
    __syncthreads();
    int node = t >> 4, c = t & 15;
    const float* crow = &Cs[node * 256];
    float a0 = bc[c], a1 = bc[c + 16], a2 = bc[c + 32], a3 = bc[c + 48];
    #pragma unroll 4
    for (int k = 0; k < 256; k++) {
        float cv = crow[k];
        const float* wr = &Ws[k * 64];
        a0 += cv * wr[c];
        a1 += cv * wr[c + 16];
        a2 += cv * wr[c + 32];
        a3 += cv * wr[c + 48];
    }
    int gn = n0 + node;
    int lab = label[gn];
    float* hr = &h[(size_t)gn * HD];
    const float* er = &emb[(size_t)lab * 64];
    hr[c]      = er[c];
    hr[c + 16] = er[c + 16];
    hr[c + 32] = er[c + 32];
    hr[c + 48] = er[c + 48];
    hr[64 + c]      = a0;
    hr[64 + c + 16] = a1;
    hr[64 + c + 32] = a2;
    hr[64 + c + 48] = a3;
}

// ---------------- tensor-core GEMM (64-row tile, pre-split bf16 inputs) ------
// out = relu(A@W + AddIn + bias) (+res)
#define APAD 136
__device__ __forceinline__ void mma16816(float c[4], const uint32_t a[4],
                                         uint32_t b0, uint32_t b1) {
    asm volatile(
        "mma.sync.aligned.m16n8k16.row.col.f32.bf16.bf16.f32 "
        "{%0,%1,%2,%3},{%4,%5,%6,%7},{%8,%9},{%0,%1,%2,%3};"
        : "+f"(c[0]), "+f"(c[1]), "+f"(c[2]), "+f"(c[3])
        : "r"(a[0]), "r"(a[1]), "r"(a[2]), "r"(a[3]), "r"(b0), "r"(b1));
}

__global__ void __launch_bounds__(256) k_gemm_mma64(
    const __nv_bfloat16* __restrict__ Ah_g, const __nv_bfloat16* __restrict__ Al_g,
    const __nv_bfloat16* __restrict__ Wh_g, const __nv_bfloat16* __restrict__ Wl_g,
    const float* __restrict__ AddIn, const float* __restrict__ bias,
    const float* __restrict__ res, float* __restrict__ out, int M, int addres)
{
    extern __shared__ __align__(16) char smraw[];
    __nv_bfloat16* Ah = (__nv_bfloat16*)smraw;     // [64][APAD]
    __nv_bfloat16* Al = Ah + 64 * APAD;
    __nv_bfloat16* Wh = Al + 64 * APAD;            // [128][APAD]  (n,k)
    __nv_bfloat16* Wl = Wh + 128 * APAD;
    int t = threadIdx.x;
    int m0 = blockIdx.x * 64;

    #pragma unroll
    for (int j = 0; j < 8; j++) {
        int i = t + 256 * j;
        int nrow = i >> 4, kg = i & 15;
        *(uint4*)&Wh[nrow * APAD + kg * 8] = ((const uint4*)Wh_g)[i];
        *(uint4*)&Wl[nrow * APAD + kg * 8] = ((const uint4*)Wl_g)[i];
    }
    #pragma unroll
    for (int j = 0; j < 4; j++) {
        int i = t + 256 * j;
        int r = i >> 4, kg = i & 15;
        long gr = m0 + r;
        uint4 vh = make_uint4(0u, 0u, 0u, 0u), vl = vh;
        if (gr < M) {
            vh = ((const uint4*)Ah_g)[gr * 16 + kg];
            vl = ((const uint4*)Al_g)[gr * 16 + kg];
        }
        *(uint4*)&Ah[r * APAD + kg * 8] = vh;
        *(uint4*)&Al[r * APAD + kg * 8] = vl;
    }
    __syncthreads();

    int warp = t >> 5, lane = t & 31;
    int wm = warp & 1, wn = warp >> 1;   // 2 M-warps x 4 N-warps
    int q = lane & 3, rr = lane >> 2;

    float c[2][4][4];
    #pragma unroll
    for (int i = 0; i < 2; i++)
        #pragma unroll
        for (int j = 0; j < 4; j++)
            c[i][j][0] = c[i][j][1] = c[i][j][2] = c[i][j][3] = 0.f;

    #pragma unroll
    for (int term = 0; term < 3; term++) {
        const __nv_bfloat16* Ab = (term == 2) ? Al : Ah;
        const __nv_bfloat16* Bb = (term == 1) ? Wl : Wh;
        #pragma unroll
        for (int ks = 0; ks < 8; ks++) {
            int kb = ks * 16;
            uint32_t a[2][4];
            #pragma unroll
            for (int mt = 0; mt < 2; mt++) {
                const __nv_bfloat16* ap = Ab + (wm * 32 + mt * 16 + rr) * APAD + kb + q * 2;
                a[mt][0] = *(const uint32_t*)(ap);
                a[mt][1] = *(const uint32_t*)(ap + 8 * APAD);
                a[mt][2] = *(const uint32_t*)(ap + 8);
                a[mt][3] = *(const uint32_t*)(ap + 8 * APAD + 8);
            }
            #pragma unroll
            for (int nt = 0; nt < 4; nt++) {
                const __nv_bfloat16* bp = Bb + (wn * 32 + nt * 8 + rr) * APAD + kb + q * 2;
                uint32_t b0 = *(const uint32_t*)bp;
                uint32_t b1 = *(const uint32_t*)(bp + 8);
                mma16816(c[0][nt], a[0], b0, b1);
                mma16816(c[1][nt], a[1], b0, b1);
            }
        }
    }

    // epilogue: + AddIn + bias, relu, (+res)
    #pragma unroll
    for (int mt = 0; mt < 2; mt++) {
        #pragma unroll
        for (int half = 0; half < 2; half++) {
            int row = m0 + wm * 32 + mt * 16 + half * 8 + rr;
            if (row >= M) continue;
            #pragma unroll
            for (int nt = 0; nt < 4; nt++) {
                int col = wn * 32 + nt * 8 + q * 2;
                size_t o = (size_t)row * HD + col;
                float2 v = make_float2(c[mt][nt][half * 2], c[mt][nt][half * 2 + 1]);
                float2 d = *(const float2*)&AddIn[o];
                float2 bb = *(const float2*)&bias[col];
                v.x += d.x + bb.x;
                v.y += d.y + bb.y;
                v.x = fmaxf(v.x, 0.f);
                v.y = fmaxf(v.y, 0.f);
                if (addres) {
                    float2 rv = *(const float2*)&res[o];
                    v.x += rv.x; v.y += rv.y;
                }
                *(float2*)&out[o] = v;
            }
        }
    }
}

// ---------------- FFMA GEMM with fused epilogue (small M) -------------------
__global__ void __launch_bounds__(256) k_gemm_ep(
    const float* __restrict__ A, const float* __restrict__ W,
    const float* __restrict__ AddIn, const float* __restrict__ bias,
    const float* __restrict__ res, float* __restrict__ out, int M, int flags)
{
    extern __shared__ float sm[];
    float* Ws = sm;            // 128*128
    float* As = sm + 16384;    // 64*132
    int t = threadIdx.x;
    const float4* W4 = (const float4*)W;
    float4* Ws4 = (float4*)Ws;
    #pragma unroll
    for (int i = 0; i < 16; i++) Ws4[t + 256 * i] = W4[t + 256 * i];
    int m0 = blockIdx.x * 64;
    #pragma unroll
    for (int i = 0; i < 8; i++) {
        int idx = t + 256 * i;
        int r = idx >> 5, cc = idx & 31;
        int gr = m0 + r;
        float4 v = (gr < M) ? ((const float4*)A)[(size_t)gr * 32 + cc]
                            : make_float4(0.f, 0.f, 0.f, 0.f);
        *(float4*)&As[r * 132 + cc * 4] = v;
    }
    __syncthreads();
    int c0 = (t & 31) * 4;
    int r0 = (t >> 5) * 8;
    float acc[8][4];
    #pragma unroll
    for (int i = 0; i < 8; i++) { acc[i][0] = acc[i][1] = acc[i][2] = acc[i][3] = 0.f; }
    #pragma unroll 2
    for (int k = 0; k < 128; k++) {
        float4 w = *(const float4*)&Ws[k * 128 + c0];
        #pragma unroll
        for (int i = 0; i < 8; i++) {
            float a = As[(r0 + i) * 132 + k];
            acc[i][0] += a * w.x;
            acc[i][1] += a * w.y;
            acc[i][2] += a * w.z;
            acc[i][3] += a * w.w;
        }
    }
    float4 bb = make_float4(0.f, 0.f, 0.f, 0.f);
    if (flags & F_BIAS) bb = *(const float4*)&bias[c0];
    #pragma unroll
    for (int i = 0; i < 8; i++) {
        int gr = m0 + r0 + i;
        if (gr < M) {
            size_t o = (size_t)gr * HD + c0;
            float4 v = make_float4(acc[i][0] + bb.x, acc[i][1] + bb.y,
                                   acc[i][2] + bb.z, acc[i][3] + bb.w);
            if (flags & F_ADDIN) {
                float4 d = *(const float4*)&AddIn[o];
                v.x += d.x; v.y += d.y; v.z += d.z; v.w += d.w;
            }
            if (flags & F_RELU) {
                v.x = fmaxf(v.x, 0.f); v.y = fmaxf(v.y, 0.f);
                v.z = fmaxf(v.z, 0.f); v.w = fmaxf(v.w, 0.f);
            }
            if (flags & F_ADDRES) {
                float4 rv = *(const float4*)&res[o];
                v.x += rv.x; v.y += rv.y; v.z += rv.z; v.w += rv.w;
            }
            *(float4*)&out[o] = v;
        }
    }
}

// ---------------- mean aggregation (fp32 out) -------------------------------
__global__ void k_agg(const float* __restrict__ X,
                      const int* __restrict__ offs, const int* __restrict__ csr,
                      float* __restrict__ out, int n)
{
    int node = (blockIdx.x * blockDim.x + threadIdx.x) >> 5;
    if (node >= n) return;
    int lane = threadIdx.x & 31;
    int s0 = offs[node], s1 = offs[node + 1];
    float4 a = make_float4(0.f, 0.f, 0.f, 0.f);
    for (int e0 = s0; e0 < s1; e0 += 32) {
        int idx = (e0 + lane < s1) ? csr[e0 + lane] : 0;
        int m = min(32, s1 - e0);
        #pragma unroll 4
        for (int j = 0; j < m; j++) {
            int s = __shfl_sync(0xffffffffu, idx, j);
            float4 v = *(const float4*)&X[(size_t)s * HD + lane * 4];
            a.x += v.x; a.y += v.y; a.z += v.z; a.w += v.w;
        }
    }
    float inv = 1.f / (float)((s1 - s0) > 0 ? (s1 - s0) : 1);
    *(float4*)&out[(size_t)node * HD + lane * 4] =
        make_float4(a.x * inv, a.y * inv, a.z * inv, a.w * inv);
}

// ---------------- mean aggregation with fused bf16 hi/lo split output -------
__global__ void k_agg_bf(const float* __restrict__ X,
                         const int* __restrict__ offs, const int* __restrict__ csr,
                         __nv_bfloat16* __restrict__ Sh, __nv_bfloat16* __restrict__ Sl,
                         int n)
{
    int node = (blockIdx.x * blockDim.x + threadIdx.x) >> 5;
    if (node >= n) return;
    int lane = threadIdx.x & 31;
    int s0 = offs[node], s1 = offs[node + 1];
    float4 a = make_float4(0.f, 0.f, 0.f, 0.f);
    for (int e0 = s0; e0 < s1; e0 += 32) {
        int idx = (e0 + lane < s1) ? csr[e0 + lane] : 0;
        int m = min(32, s1 - e0);
        #pragma unroll 4
        for (int j = 0; j < m; j++) {
            int s = __shfl_sync(0xffffffffu, idx, j);
            float4 v = *(const float4*)&X[(size_t)s * HD + lane * 4];
            a.x += v.x; a.y += v.y; a.z += v.z; a.w += v.w;
        }
    }
    float inv = 1.f / (float)((s1 - s0) > 0 ? (s1 - s0) : 1);
    const float mv[4] = {a.x * inv, a.y * inv, a.z * inv, a.w * inv};
    __nv_bfloat16 hh[4], ll[4];
    #pragma unroll
    for (int u = 0; u < 4; u++) {
        hh[u] = __float2bfloat16_rn(mv[u]);
        ll[u] = __float2bfloat16_rn(mv[u] - __bfloat162float(hh[u]));
    }
    size_t o = (size_t)node * HD + lane * 4;
    *(uint2*)&Sh[o] = *(uint2*)hh;
    *(uint2*)&Sl[o] = *(uint2*)ll;
}

// ---------------- decoder ----------------------------------------------------
__global__ void k_decode(const float* __restrict__ h, const float* __restrict__ dW,
                         const float* __restrict__ db, float* __restrict__ logits,
                         float* __restrict__ pred, int write_pred)
{
    int node = (blockIdx.x * blockDim.x + threadIdx.x) >> 5;
    if (node >= N_AST) return;
    int lane = threadIdx.x & 31;
    float4 v = *(const float4*)&h[(size_t)node * HD + lane * 4];
    float l0 = 0.f, l1 = 0.f;
    const float* hv = &v.x;
    #pragma unroll
    for (int j = 0; j < 4; j++) {
        int k = lane * 4 + j;
        float2 w = *(const float2*)&dW[k * 2];
        l0 += hv[j] * w.x;
        l1 += hv[j] * w.y;
    }
    #pragma unroll
    for (int o = 16; o; o >>= 1) {
        l0 += __shfl_xor_sync(0xffffffffu, l0, o);
        l1 += __shfl_xor_sync(0xffffffffu, l1, o);
    }
    if (lane == 0) {
        l0 += db[0];
        l1 += db[1];
        logits[node * 2]     = l0;
        logits[node * 2 + 1] = l1;
        if (write_pred) {
            float m = fmaxf(l0, l1);
            float e0 = expf(l0 - m), e1 = expf(l1 - m);
            float s = e0 + e1;
            pred[node * 2]     = e0 / s;
            pred[node * 2 + 1] = e1 / s;
        }
    }
}

// ---------------- launch ----------------------------------------------------
extern "C" void kernel_launch(void* const* d_in, const int* in_sizes, int n_in,
                              void* d_out, int out_size)
{
    const int*   ast_label   = (const int*)d_in[0];
    const float* ast_content = (const float*)d_in[1];
    const int* src_aa = (const int*)d_in[2];
    const int* dst_aa = (const int*)d_in[3];
    const int* src_at = (const int*)d_in[4];
    const int* dst_at = (const int*)d_in[5];
    const int* src_ta = (const int*)d_in[6];
    const int* dst_ta = (const int*)d_in[7];
    int E_aa = in_sizes[2], E_at = in_sizes[4], E_ta = in_sizes[6];

    int p = 8;
    if (n_in > 8 && in_sizes[8] == 1) p = 9;
    const float* emb    = (const float*)d_in[p + 0];
    const float* Wc     = (const float*)d_in[p + 1];
    const float* bc     = (const float*)d_in[p + 2];
    const float* temb   = (const float*)d_in[p + 3];
    const float* W_aa   = (const float*)d_in[p + 4];
    const float* W_at   = (const float*)d_in[p + 5];
    const float* W_ta   = (const float*)d_in[p + 6];
    const float* b_ast  = (const float*)d_in[p + 7];
    const float* b_test = (const float*)d_in[p + 8];
    const float* dW     = (const float*)d_in[p + 9];
    const float* db     = (const float*)d_in[p + 10];

    float* F = nullptr;
    int*   I = nullptr;
    cudaGetSymbolAddress((void**)&F, g_f);
    cudaGetSymbolAddress((void**)&I, g_i);

    cudaFuncSetAttribute(k_gemm_ep,    cudaFuncAttributeMaxDynamicSharedMemorySize, 99328);
    cudaFuncSetAttribute(k_gemm_mma64, cudaFuncAttributeMaxDynamicSharedMemorySize, 104448);
    cudaFuncSetAttribute(k_encode,     cudaFuncAttributeMaxDynamicSharedMemorySize, 81920);

    float* hA  = F + F_HA;   float* hB  = F + F_HB;
    __nv_bfloat16* Sh = (__nv_bfloat16*)(F + F_SH);
    __nv_bfloat16* Sl = (__nv_bfloat16*)(F + F_SL);
    float* Mta = F + F_MTA;
    float* Xta = F + F_XTA;  float* St  = F + F_STB;
    float* hTA = F + F_HTA;  float* hTB = F + F_HTB;
    __nv_bfloat16* Whg = (__nv_bfloat16*)(F + F_WS);
    __nv_bfloat16* Wlg = (__nv_bfloat16*)(F + F_WS + 40960u);

    int* off_aa = I + I_OFF_AA; int* off_ta = I + I_OFF_TA; int* off_at = I + I_OFF_AT;
    int* cur_aa = I + I_CUR_AA; int* cur_ta = I + I_CUR_TA; int* cur_at = I + I_CUR_AT;
    int* csr_aa = I + I_CSR_AA; int* csr_ta = I + I_CSR_TA; int* csr_at = I + I_CSR_AT;
    int* part   = I + I_PART;   int* poff   = I + I_POFF;

    int nb_ast  = div_up(N_AST, 1024);
    int nb_test = div_up(N_TEST, 1024);

    // --- CSR build ---
    k_zero_int<<<div_up(N_AST, 256), 256>>>(cur_aa, N_AST);
    k_zero_int<<<div_up(N_AST, 256), 256>>>(cur_ta, N_AST);
    k_zero_int<<<div_up(N_TEST, 256), 256>>>(cur_at, N_TEST);
    k_hist<<<div_up(E_aa, 256), 256>>>(dst_aa, cur_aa, E_aa);
    k_hist<<<div_up(E_ta, 256), 256>>>(dst_ta, cur_ta, E_ta);
    k_hist<<<div_up(E_at, 256), 256>>>(dst_at, cur_at, E_at);
    k_blocksum<<<nb_ast, 1024>>>(cur_aa, part, N_AST);
    k_exscan<<<1, 1024>>>(part, poff, nb_ast);
    k_scan_apply<<<nb_ast, 1024>>>(cur_aa, poff, off_aa, cur_aa, N_AST);
    k_blocksum<<<nb_ast, 1024>>>(cur_ta, part, N_AST);
    k_exscan<<<1, 1024>>>(part, poff, nb_ast);
    k_scan_apply<<<nb_ast, 1024>>>(cur_ta, poff, off_ta, cur_ta, N_AST);
    k_blocksum<<<nb_test, 1024>>>(cur_at, part, N_TEST);
    k_exscan<<<1, 1024>>>(part, poff, nb_test);
    k_scan_apply<<<nb_test, 1024>>>(cur_at, poff, off_at, cur_at, N_TEST);
    k_build<<<div_up(E_aa, 256), 256>>>(dst_aa, src_aa, cur_aa, csr_aa, E_aa);
    k_build<<<div_up(E_ta, 256), 256>>>(dst_ta, src_ta, cur_ta, csr_ta, E_ta);
    k_build<<<div_up(E_at, 256), 256>>>(dst_at, src_at, cur_at, csr_at, E_at);

    // --- weight pre-split + encode ---
    k_split_w<<<div_up(NLAYERS * 16384, 256), 256>>>(W_aa, Whg, Wlg);
    k_encode<<<N_AST / 16, 256, 81920>>>(ast_label, ast_content, emb, Wc, bc, hA);
    k_init_test<<<div_up(N_TEST * HD, 256), 256>>>(temb, hTA);

    // --- 5 GCN layers ---
    const float* ia = hA; const float* it = hTA;
    float* oa = hB; float* ot = hTB;
    for (int l = 0; l < NLAYERS; l++) {
        int add  = (l == 1 || l == 3);
        int last = (l == NLAYERS - 1);
        // Sh/Sl = split(mean_aa(ia)); St = mean_at(ia)
        k_agg_bf<<<div_up(N_AST * 32, 256), 256>>>(ia, off_aa, csr_aa, Sh, Sl, N_AST);
        if (!last)
            k_agg<<<div_up(N_TEST * 32, 256), 256>>>(ia, off_at, csr_at, St, N_TEST);
        // Xta = h_test @ W_ta; Mta = mean_ta(Xta)
        k_gemm_ep<<<div_up(N_TEST, 64), 256, 99328>>>(it, W_ta + (size_t)l * HD * HD,
            nullptr, nullptr, nullptr, Xta, N_TEST, 0);
        k_agg<<<div_up(N_AST * 32, 256), 256>>>(Xta, off_ta, csr_ta, Mta, N_AST);
        // h_ast' = relu(S @ W_aa + Mta + b_ast) (+ia)   [tensor cores]
        k_gemm_mma64<<<div_up(N_AST, 64), 256, 104448>>>(Sh, Sl,
            Whg + (size_t)l * 16384, Wlg + (size_t)l * 16384,
            Mta, b_ast + l * HD, ia, oa, N_AST, add);
        // h_test' = relu(St @ W_at + b_test) (+it)   [dead at last layer]
        if (!last)
            k_gemm_ep<<<div_up(N_TEST, 64), 256, 99328>>>(St, W_at + (size_t)l * HD * HD,
                nullptr, b_test + l * HD, it, ot, N_TEST,
                F_BIAS | F_RELU | (add ? F_ADDRES : 0));
        const float* ta = ia; ia = oa; oa = (float*)ta;
        if (!last) { const float* tt = it; it = ot; ot = (float*)tt; }
    }

    // --- decode ---
    float* logits = (float*)d_out;
    int write_pred = (out_size >= 4 * N_AST);
    float* pred = logits + 2 * N_AST;
    k_decode<<<div_up(N_AST * 32, 256), 256>>>(ia, dW, db, logits, pred, write_pred);
}